// round 1
// baseline (speedup 1.0000x reference)
#include <cuda_runtime.h>
#include <cuda_bf16.h>

// Fused species-routed MLP over AEV features.
//   fullaev [B=1024, A=256, 384] f32
//   species [A] i32
//   Wj [S=4, in_j, out_j], bj [S, out_j]  (sizes 384->256->192->160->1)
// Per block: one atom, one 64-row B-tile. Activations ping-pong in SMEM.
// Atom-sum done deterministically via a __device__ scratch + reduce kernel.

#define ALPHA_CELU 0.1f

__device__ float g_partial[256 * 1024];  // [atom][b] partial molecule sums

__device__ __forceinline__ float celu_f(float x) {
    return x > 0.f ? x : ALPHA_CELU * expm1f(x * (1.f / ALPHA_CELU));
}

// Y[64, N] = celu(X[64, K] * W[K, N] + bias), X/Y in shared (padded strides),
// W/bias in global (L2-resident). 256 threads as 16(ty: 4 rows each) x 16(tx: TN cols each).
template<int K, int N, int TN, int LDX, int LDY>
__device__ __forceinline__ void layer_gemm(
    const float* __restrict__ W, const float* __restrict__ bias_g,
    const float* __restrict__ xs, float* __restrict__ ys, int tid)
{
    const int ty = tid >> 4;   // 0..15 -> rows ty*4 .. ty*4+3
    const int tx = tid & 15;   // 0..15 -> cols tx*TN .. tx*TN+TN-1

    float acc[4][TN];
#pragma unroll
    for (int r = 0; r < 4; r++)
#pragma unroll
        for (int j = 0; j < TN; j++) acc[r][j] = 0.f;

    const float* wp = W + tx * TN;            // W[k*N + tx*TN + j]
    const float* xp = xs + (ty * 4) * LDX;

#pragma unroll 4
    for (int k = 0; k < K; k++) {
        float xv[4];
#pragma unroll
        for (int r = 0; r < 4; r++) xv[r] = xp[r * LDX + k];

        float wv[TN];
        if constexpr (TN % 4 == 0) {
#pragma unroll
            for (int j = 0; j < TN / 4; j++) {
                float4 t = *(const float4*)(wp + (size_t)k * N + j * 4);
                wv[4 * j + 0] = t.x; wv[4 * j + 1] = t.y;
                wv[4 * j + 2] = t.z; wv[4 * j + 3] = t.w;
            }
        } else {
#pragma unroll
            for (int j = 0; j < TN / 2; j++) {
                float2 t = *(const float2*)(wp + (size_t)k * N + j * 2);
                wv[2 * j + 0] = t.x; wv[2 * j + 1] = t.y;
            }
        }

#pragma unroll
        for (int r = 0; r < 4; r++)
#pragma unroll
            for (int j = 0; j < TN; j++)
                acc[r][j] = fmaf(xv[r], wv[j], acc[r][j]);
    }

    float bb[TN];
#pragma unroll
    for (int j = 0; j < TN; j++) bb[j] = bias_g[tx * TN + j];

#pragma unroll
    for (int r = 0; r < 4; r++) {
        float* yp = ys + (ty * 4 + r) * LDY + tx * TN;
#pragma unroll
        for (int j = 0; j < TN; j++)
            yp[j] = celu_f(acc[r][j] + bb[j]);
    }
}

// SMEM strides (padded, multiples of 4 for float4 access)
#define LD_IN  388   // layer0 input  (384 cols)
#define LD_L0  260   // layer0 output (256 cols)
#define LD_L1  196   // layer1 output (192 cols)
#define LD_L2  164   // layer2 output (160 cols)
#define SMEM_FLOATS (64 * LD_IN + 64 * LD_L0)

__global__ __launch_bounds__(256, 1)
void aev_mlp_kernel(const float* __restrict__ fullaev, const int* __restrict__ species,
                    const float* __restrict__ W0, const float* __restrict__ b0,
                    const float* __restrict__ W1, const float* __restrict__ b1,
                    const float* __restrict__ W2, const float* __restrict__ b2,
                    const float* __restrict__ W3, const float* __restrict__ b3)
{
    extern __shared__ float smem[];
    float* buf0 = smem;             // stride LD_IN, later reused with stride LD_L1
    float* buf1 = smem + 64 * LD_IN; // stride LD_L0, later reused with stride LD_L2

    const int a = blockIdx.y;        // atom 0..255
    const int bbase = blockIdx.x * 64;
    const int tid = threadIdx.x;
    const int s = species[a];

    // Load X tile [64 rows x 384] into buf0 (row r = molecule bbase+r)
    const float* xg = fullaev + (size_t)bbase * (256 * 384) + (size_t)a * 384;
    for (int i = tid; i < 64 * 96; i += 256) {
        int r = i / 96;
        int c = (i % 96) * 4;
        float4 v = *(const float4*)(xg + (size_t)r * (256 * 384) + c);
        float* d = buf0 + r * LD_IN + c;
        d[0] = v.x; d[1] = v.y; d[2] = v.z; d[3] = v.w;
    }
    __syncthreads();

    layer_gemm<384, 256, 16, LD_IN, LD_L0>(W0 + (size_t)s * 384 * 256, b0 + s * 256, buf0, buf1, tid);
    __syncthreads();
    layer_gemm<256, 192, 12, LD_L0, LD_L1>(W1 + (size_t)s * 256 * 192, b1 + s * 192, buf1, buf0, tid);
    __syncthreads();
    layer_gemm<192, 160, 10, LD_L1, LD_L2>(W2 + (size_t)s * 192 * 160, b2 + s * 160, buf0, buf1, tid);
    __syncthreads();

    // Layer 3: N=1 (dot with w3[160]) + celu, write per-atom partial
    if (tid < 64) {
        const float* w = W3 + s * 160;   // [S,160,1]
        float acc = b3[s];               // [S,1]
        const float* xr = buf1 + tid * LD_L2;
#pragma unroll 8
        for (int k = 0; k < 160; k++) acc = fmaf(xr[k], w[k], acc);
        g_partial[a * 1024 + bbase + tid] = celu_f(acc);
    }
}

__global__ void reduce_atoms_kernel(float* __restrict__ out) {
    int b = blockIdx.x * blockDim.x + threadIdx.x;   // 0..1023
    float acc = 0.f;
#pragma unroll 8
    for (int a = 0; a < 256; a++) acc += g_partial[a * 1024 + b];
    out[b] = acc;
}

extern "C" void kernel_launch(void* const* d_in, const int* in_sizes, int n_in,
                              void* d_out, int out_size) {
    const float* fullaev = (const float*)d_in[0];
    const int*   species = (const int*)d_in[1];
    const float* W0 = (const float*)d_in[2];
    const float* b0 = (const float*)d_in[3];
    const float* W1 = (const float*)d_in[4];
    const float* b1 = (const float*)d_in[5];
    const float* W2 = (const float*)d_in[6];
    const float* b2 = (const float*)d_in[7];
    const float* W3 = (const float*)d_in[8];
    const float* b3 = (const float*)d_in[9];

    const int smem_bytes = SMEM_FLOATS * (int)sizeof(float);
    cudaFuncSetAttribute(aev_mlp_kernel,
                         cudaFuncAttributeMaxDynamicSharedMemorySize, smem_bytes);

    dim3 grid(1024 / 64, 256);   // (B-tiles, atoms)
    aev_mlp_kernel<<<grid, 256, smem_bytes>>>(fullaev, species,
                                              W0, b0, W1, b1, W2, b2, W3, b3);
    reduce_atoms_kernel<<<4, 256>>>((float*)d_out);
}

// round 3
// speedup vs baseline: 4.0902x; 4.0902x over previous
#include <cuda_runtime.h>
#include <cstdint>
#include <math.h>

#define ALPHA_CELU 0.1f

// ---------------- device scratch ----------------
__device__ float g_partial[256 * 1024];   // [atom][b]
__device__ float g_red[8 * 1024];

// ---------------- helpers ----------------
__device__ __forceinline__ float celu_f(float x) {
    return x > 0.f ? x : ALPHA_CELU * expm1f(x * (1.f / ALPHA_CELU));
}
__device__ __forceinline__ uint32_t tf32r(float x) {      // round-to-nearest tf32
    uint32_t u;
    asm("cvt.rna.tf32.f32 %0, %1;" : "=r"(u) : "f"(x));
    return u;
}
__device__ __forceinline__ void mma_tf32(float c[4],
                                         uint32_t a0, uint32_t a1, uint32_t a2, uint32_t a3,
                                         uint32_t b0, uint32_t b1) {
    asm volatile("mma.sync.aligned.m16n8k8.row.col.f32.tf32.tf32.f32 "
                 "{%0,%1,%2,%3}, {%4,%5,%6,%7}, {%8,%9}, {%0,%1,%2,%3};"
                 : "+f"(c[0]), "+f"(c[1]), "+f"(c[2]), "+f"(c[3])
                 : "r"(a0), "r"(a1), "r"(a2), "r"(a3), "r"(b0), "r"(b1));
}

// ---------------- smem layout (floats) ----------------
// Ys: 128 x <=256, stride 260 (260%32==4 -> conflict-free A frags)
// Xc: 128 x 16,     stride 20  (20%32 ==4... per-instr distinct, see analysis)
// Wc: 16  x <=256,  stride 264 (264%32==8 -> conflict-free B frags)
#define LDY 260
#define LDX 20
#define LDW 264
#define OFF_X (128 * LDY)
#define OFF_W (OFF_X + 128 * LDX)
#define SMEM_FLOATS (OFF_W + 16 * LDW)
#define SMEM_BYTES (SMEM_FLOATS * 4)

// ---------------- one MLP layer: Y[128,N] = celu(A[128,K] @ W + b) ----------------
// A source: L0 ? staged X chunks from gmem : resident Ys.
// Warp grid 2(m) x 4(n); warp tile 64 x N/4. ROUND: tf32-round outputs.
template<int K, int N, bool L0, bool ROUND>
__device__ __forceinline__ void layer_run(
    const float* __restrict__ Wg, const float* __restrict__ bg,
    const float* __restrict__ xg,
    float* __restrict__ Ys, float* __restrict__ Xc, float* __restrict__ Wc,
    int tid, int lane, int m_idx, int n_idx)
{
    constexpr int NT = N / 32;              // n8 tiles per warp
    constexpr int NC = K / 16;              // k chunks
    constexpr int TOTW = 16 * N / 4;        // float4s per W chunk
    constexpr int WPT = (TOTW + 255) / 256;

    float acc[4][NT][4];
#pragma unroll
    for (int f = 0; f < 4; f++)
#pragma unroll
        for (int t = 0; t < NT; t++)
#pragma unroll
            for (int j = 0; j < 4; j++) acc[f][t][j] = 0.f;

    const int xr_row = tid >> 1, xr_q = (tid & 1) * 8;   // X staging: 2 thr/row, 8 floats each

    float4 wst[WPT];
    float4 xst[2];

    // ---- stage chunk 0 ----
#pragma unroll
    for (int j = 0; j < WPT; j++) {
        int i = tid + j * 256;
        if (i < TOTW) {
            int k = i / (N / 4), n4 = (i % (N / 4)) * 4;
            wst[j] = *(const float4*)(Wg + (size_t)k * N + n4);
        }
    }
    if (L0) {
        xst[0] = *(const float4*)(xg + (size_t)xr_row * 98304 + xr_q);
        xst[1] = *(const float4*)(xg + (size_t)xr_row * 98304 + xr_q + 4);
    }
#pragma unroll
    for (int j = 0; j < WPT; j++) {
        int i = tid + j * 256;
        if (i < TOTW) {
            int k = i / (N / 4), n4 = (i % (N / 4)) * 4;
            uint4 v = { tf32r(wst[j].x), tf32r(wst[j].y), tf32r(wst[j].z), tf32r(wst[j].w) };
            *(uint4*)(Wc + k * LDW + n4) = v;
        }
    }
    if (L0) {
        uint4 v0 = { tf32r(xst[0].x), tf32r(xst[0].y), tf32r(xst[0].z), tf32r(xst[0].w) };
        uint4 v1 = { tf32r(xst[1].x), tf32r(xst[1].y), tf32r(xst[1].z), tf32r(xst[1].w) };
        *(uint4*)(Xc + xr_row * LDX + xr_q) = v0;
        *(uint4*)(Xc + xr_row * LDX + xr_q + 4) = v1;
    }
    __syncthreads();

    for (int c = 0; c < NC; c++) {
        // ---- prefetch chunk c+1 into registers ----
        if (c + 1 < NC) {
#pragma unroll
            for (int j = 0; j < WPT; j++) {
                int i = tid + j * 256;
                if (i < TOTW) {
                    int k = i / (N / 4), n4 = (i % (N / 4)) * 4;
                    wst[j] = *(const float4*)(Wg + (size_t)((c + 1) * 16 + k) * N + n4);
                }
            }
            if (L0) {
                int kb = (c + 1) * 16;
                xst[0] = *(const float4*)(xg + (size_t)xr_row * 98304 + kb + xr_q);
                xst[1] = *(const float4*)(xg + (size_t)xr_row * 98304 + kb + xr_q + 4);
            }
        }

        // ---- compute chunk c (two k8 steps) ----
#pragma unroll
        for (int kk = 0; kk < 2; kk++) {
            uint32_t af[4][4];
            if (L0) {
                const int cc = kk * 8 + (lane & 3);
#pragma unroll
                for (int f = 0; f < 4; f++) {
                    int r = m_idx * 64 + f * 16 + (lane >> 2);
                    af[f][0] = __float_as_uint(Xc[r * LDX + cc]);
                    af[f][1] = __float_as_uint(Xc[(r + 8) * LDX + cc]);
                    af[f][2] = __float_as_uint(Xc[r * LDX + cc + 4]);
                    af[f][3] = __float_as_uint(Xc[(r + 8) * LDX + cc + 4]);
                }
            } else {
                const int cc = c * 16 + kk * 8 + (lane & 3);
#pragma unroll
                for (int f = 0; f < 4; f++) {
                    int r = m_idx * 64 + f * 16 + (lane >> 2);
                    af[f][0] = __float_as_uint(Ys[r * LDY + cc]);
                    af[f][1] = __float_as_uint(Ys[(r + 8) * LDY + cc]);
                    af[f][2] = __float_as_uint(Ys[r * LDY + cc + 4]);
                    af[f][3] = __float_as_uint(Ys[(r + 8) * LDY + cc + 4]);
                }
            }
#pragma unroll
            for (int t = 0; t < NT; t++) {
                const int nb = n_idx * (N / 4) + t * 8 + (lane >> 2);
                uint32_t b0 = __float_as_uint(Wc[(kk * 8 + (lane & 3)) * LDW + nb]);
                uint32_t b1 = __float_as_uint(Wc[(kk * 8 + 4 + (lane & 3)) * LDW + nb]);
#pragma unroll
                for (int f = 0; f < 4; f++)
                    mma_tf32(acc[f][t], af[f][0], af[f][1], af[f][2], af[f][3], b0, b1);
            }
        }
        __syncthreads();   // all warps done reading smem chunk c

        // ---- store prefetched chunk c+1 ----
        if (c + 1 < NC) {
#pragma unroll
            for (int j = 0; j < WPT; j++) {
                int i = tid + j * 256;
                if (i < TOTW) {
                    int k = i / (N / 4), n4 = (i % (N / 4)) * 4;
                    uint4 v = { tf32r(wst[j].x), tf32r(wst[j].y), tf32r(wst[j].z), tf32r(wst[j].w) };
                    *(uint4*)(Wc + k * LDW + n4) = v;
                }
            }
            if (L0) {
                uint4 v0 = { tf32r(xst[0].x), tf32r(xst[0].y), tf32r(xst[0].z), tf32r(xst[0].w) };
                uint4 v1 = { tf32r(xst[1].x), tf32r(xst[1].y), tf32r(xst[1].z), tf32r(xst[1].w) };
                *(uint4*)(Xc + xr_row * LDX + xr_q) = v0;
                *(uint4*)(Xc + xr_row * LDX + xr_q + 4) = v1;
            }
            __syncthreads();
        }
    }

    // ---- epilogue: bias + celu (+ tf32 round), write to Ys ----
#pragma unroll
    for (int f = 0; f < 4; f++) {
#pragma unroll
        for (int t = 0; t < NT; t++) {
            int r = m_idx * 64 + f * 16 + (lane >> 2);
            int cb = n_idx * (N / 4) + t * 8 + 2 * (lane & 3);
            float bv0 = __ldg(bg + cb), bv1 = __ldg(bg + cb + 1);
            float v0 = celu_f(acc[f][t][0] + bv0);
            float v1 = celu_f(acc[f][t][1] + bv1);
            float v2 = celu_f(acc[f][t][2] + bv0);
            float v3 = celu_f(acc[f][t][3] + bv1);
            if (ROUND) {
                v0 = __uint_as_float(tf32r(v0)); v1 = __uint_as_float(tf32r(v1));
                v2 = __uint_as_float(tf32r(v2)); v3 = __uint_as_float(tf32r(v3));
            }
            Ys[r * LDY + cb] = v0;
            Ys[r * LDY + cb + 1] = v1;
            Ys[(r + 8) * LDY + cb] = v2;
            Ys[(r + 8) * LDY + cb + 1] = v3;
        }
    }
    __syncthreads();
}

// ---------------- fused kernel ----------------
__global__ void __launch_bounds__(256, 1)
aev_mlp_mma(const float* __restrict__ fullaev, const int* __restrict__ species,
            const float* __restrict__ W0, const float* __restrict__ b0,
            const float* __restrict__ W1, const float* __restrict__ b1,
            const float* __restrict__ W2, const float* __restrict__ b2,
            const float* __restrict__ W3, const float* __restrict__ b3)
{
    extern __shared__ float sm[];
    float* Ys = sm;
    float* Xc = sm + OFF_X;
    float* Wc = sm + OFF_W;

    const int a = blockIdx.y;
    const int bbase = blockIdx.x * 128;
    const int tid = threadIdx.x;
    const int lane = tid & 31, wid = tid >> 5;
    const int m_idx = wid >> 2, n_idx = wid & 3;
    const int s = species[a];
    const float* xg = fullaev + (size_t)bbase * 98304 + (size_t)a * 384;

    layer_run<384, 256, true,  true >(W0 + (size_t)s * 384 * 256, b0 + s * 256, xg, Ys, Xc, Wc, tid, lane, m_idx, n_idx);
    layer_run<256, 192, false, true >(W1 + (size_t)s * 256 * 192, b1 + s * 192, xg, Ys, Xc, Wc, tid, lane, m_idx, n_idx);
    layer_run<192, 160, false, false>(W2 + (size_t)s * 192 * 160, b2 + s * 160, xg, Ys, Xc, Wc, tid, lane, m_idx, n_idx);

    // ---- layer 3: dot(Y2[r,:160], w3) + b3, celu, per-atom partial ----
    if (tid < 128) {
        const float* w = W3 + s * 160;
        float a0 = 0.f, a1 = 0.f, a2 = 0.f, a3 = 0.f;
        const float* yr = Ys + tid * LDY;
#pragma unroll
        for (int k = 0; k < 160; k += 4) {
            a0 = fmaf(yr[k + 0], __ldg(w + k + 0), a0);
            a1 = fmaf(yr[k + 1], __ldg(w + k + 1), a1);
            a2 = fmaf(yr[k + 2], __ldg(w + k + 2), a2);
            a3 = fmaf(yr[k + 3], __ldg(w + k + 3), a3);
        }
        float acc = ((a0 + a1) + (a2 + a3)) + __ldg(b3 + s);
        g_partial[(size_t)a * 1024 + bbase + tid] = celu_f(acc);
    }
}

// ---------------- deterministic two-stage reduction ----------------
__global__ void reduce1() {
    int b = blockIdx.x * 256 + threadIdx.x;
    int ag = blockIdx.y;
    float acc = 0.f;
#pragma unroll
    for (int i = 0; i < 32; i++) acc += g_partial[(size_t)(ag * 32 + i) * 1024 + b];
    g_red[ag * 1024 + b] = acc;
}
__global__ void reduce2(float* __restrict__ out) {
    int b = blockIdx.x * 256 + threadIdx.x;
    float acc = 0.f;
#pragma unroll
    for (int g = 0; g < 8; g++) acc += g_red[g * 1024 + b];
    out[b] = acc;
}

extern "C" void kernel_launch(void* const* d_in, const int* in_sizes, int n_in,
                              void* d_out, int out_size) {
    const float* fullaev = (const float*)d_in[0];
    const int*   species = (const int*)d_in[1];
    const float* W0 = (const float*)d_in[2];
    const float* b0 = (const float*)d_in[3];
    const float* W1 = (const float*)d_in[4];
    const float* b1 = (const float*)d_in[5];
    const float* W2 = (const float*)d_in[6];
    const float* b2 = (const float*)d_in[7];
    const float* W3 = (const float*)d_in[8];
    const float* b3 = (const float*)d_in[9];

    cudaFuncSetAttribute(aev_mlp_mma, cudaFuncAttributeMaxDynamicSharedMemorySize, SMEM_BYTES);
    dim3 grid(8, 256);   // (B-tiles of 128, atoms)
    aev_mlp_mma<<<grid, 256, SMEM_BYTES>>>(fullaev, species, W0, b0, W1, b1, W2, b2, W3, b3);

    reduce1<<<dim3(4, 8), 256>>>();
    reduce2<<<4, 256>>>((float*)d_out);
}